// round 2
// baseline (speedup 1.0000x reference)
#include <cuda_runtime.h>

#define BB 8
#define TT 2048
#define CC 1024
#define HH 64

// scratch for projected q, k, v (allocation-free rule -> device globals)
__device__ float g_q[BB*TT*HH];
__device__ float g_k[BB*TT*HH];
__device__ float g_v[BB*TT*HH];

// ---------------------------------------------------------------------------
// Projection: q/k/v = x @ Wq/Wk/Wv, fused (x read once).
// Block: 256 threads = 16x16, each thread computes 4x4 per output matrix.
// M tile = 64 rows, N = 64 (full H), K chunked by 32 through smem.
// ---------------------------------------------------------------------------
__global__ __launch_bounds__(256, 1) void proj_kernel(
    const float* __restrict__ x, const float* __restrict__ Wq,
    const float* __restrict__ Wk, const float* __restrict__ Wv)
{
    __shared__ float xs[64][33];       // +1 pad
    __shared__ float wq_s[32][64];
    __shared__ float wk_s[32][64];
    __shared__ float wv_s[32][64];

    const int tid = threadIdx.x;
    const int ty = tid >> 4, tx = tid & 15;
    const size_t row0 = (size_t)blockIdx.x * 64;

    float aq[4][4] = {}, ak[4][4] = {}, av[4][4] = {};

    for (int k0 = 0; k0 < CC; k0 += 32) {
        __syncthreads();
        #pragma unroll
        for (int i = 0; i < 8; i++) {
            int idx = tid + i*256;
            int r = idx >> 5, c = idx & 31;
            xs[r][c] = x[(row0 + r)*CC + (k0 + c)];
        }
        #pragma unroll
        for (int i = 0; i < 8; i++) {
            int idx = tid + i*256;
            int r = idx >> 6, c = idx & 63;
            wq_s[r][c] = Wq[(size_t)(k0 + r)*HH + c];
            wk_s[r][c] = Wk[(size_t)(k0 + r)*HH + c];
            wv_s[r][c] = Wv[(size_t)(k0 + r)*HH + c];
        }
        __syncthreads();
        #pragma unroll
        for (int kk = 0; kk < 32; kk++) {
            float a[4];
            #pragma unroll
            for (int i = 0; i < 4; i++) a[i] = xs[ty*4+i][kk];
            float4 bq = *(const float4*)&wq_s[kk][tx*4];
            float4 bk = *(const float4*)&wk_s[kk][tx*4];
            float4 bv = *(const float4*)&wv_s[kk][tx*4];
            #pragma unroll
            for (int i = 0; i < 4; i++) {
                aq[i][0] += a[i]*bq.x; aq[i][1] += a[i]*bq.y;
                aq[i][2] += a[i]*bq.z; aq[i][3] += a[i]*bq.w;
                ak[i][0] += a[i]*bk.x; ak[i][1] += a[i]*bk.y;
                ak[i][2] += a[i]*bk.z; ak[i][3] += a[i]*bk.w;
                av[i][0] += a[i]*bv.x; av[i][1] += a[i]*bv.y;
                av[i][2] += a[i]*bv.z; av[i][3] += a[i]*bv.w;
            }
        }
    }
    #pragma unroll
    for (int i = 0; i < 4; i++) {
        size_t off = (row0 + ty*4 + i)*HH + tx*4;
        *(float4*)&g_q[off] = make_float4(aq[i][0],aq[i][1],aq[i][2],aq[i][3]);
        *(float4*)&g_k[off] = make_float4(ak[i][0],ak[i][1],ak[i][2],ak[i][3]);
        *(float4*)&g_v[off] = make_float4(av[i][0],av[i][1],av[i][2],av[i][3]);
    }
}

// ---------------------------------------------------------------------------
// Flash attention (causal), Br = Bc = 64, fp32.
// Grid: (T/64, B). Block: 256 threads = 16x16; each thread owns 4 rows x 4 cols
// of both S (64x64) and O (64x64). Row reductions via shfl within the 16-lane
// thread-row (stays inside a half-warp). Only kt <= qt tiles are visited.
// ---------------------------------------------------------------------------
__global__ __launch_bounds__(256, 1) void attn_kernel(float* __restrict__ out)
{
    extern __shared__ float sm[];
    float* Qs = sm;                  // 64 x 65
    float* Ks = Qs + 64*65;          // 64 x 65
    float* Ss = Ks + 64*65;          // 64 x 65 (P tile)
    float* Vs = Ss + 64*65;          // 64 x 64 (stride 64 for aligned float4)

    const int tid = threadIdx.x;
    const int ty = tid >> 4, tx = tid & 15;
    const int b  = blockIdx.y;
    const int qt = blockIdx.x;
    const int r0 = qt*64;
    const float* qg = g_q + (size_t)b*TT*HH;
    const float* kg = g_k + (size_t)b*TT*HH;
    const float* vg = g_v + (size_t)b*TT*HH;

    #pragma unroll
    for (int i = 0; i < 16; i++) {
        int idx = tid + i*256;
        int r = idx >> 6, c = idx & 63;
        Qs[r*65+c] = qg[(size_t)(r0 + r)*HH + c];
    }

    float o[4][4] = {};
    float m_i[4] = {-1e30f, -1e30f, -1e30f, -1e30f};
    float l_i[4] = {};

    for (int kt = 0; kt <= qt; kt++) {
        const int c0 = kt*64;
        __syncthreads();   // protect Ks/Vs/Ss from previous iteration's readers
        #pragma unroll
        for (int i = 0; i < 16; i++) {
            int idx = tid + i*256;
            int r = idx >> 6, c = idx & 63;
            Ks[r*65+c] = kg[(size_t)(c0 + r)*HH + c];
            Vs[r*64+c] = vg[(size_t)(c0 + r)*HH + c];
        }
        __syncthreads();

        // S = Q K^T  (4x4 per thread)
        float s[4][4] = {};
        #pragma unroll
        for (int h = 0; h < HH; h++) {
            float a[4], bk[4];
            #pragma unroll
            for (int i = 0; i < 4; i++) a[i]  = Qs[(ty*4+i)*65 + h];
            #pragma unroll
            for (int j = 0; j < 4; j++) bk[j] = Ks[(tx*4+j)*65 + h];
            #pragma unroll
            for (int i = 0; i < 4; i++)
                #pragma unroll
                for (int j = 0; j < 4; j++)
                    s[i][j] += a[i]*bk[j];
        }

        const float scale = 0.125f;  // 1/sqrt(64)
        if (kt == qt) {
            #pragma unroll
            for (int i = 0; i < 4; i++)
                #pragma unroll
                for (int j = 0; j < 4; j++)
                    s[i][j] = (c0 + tx*4 + j > r0 + ty*4 + i) ? -1e30f
                                                              : s[i][j]*scale;
        } else {
            #pragma unroll
            for (int i = 0; i < 4; i++)
                #pragma unroll
                for (int j = 0; j < 4; j++)
                    s[i][j] *= scale;
        }

        // online softmax update per owned row
        #pragma unroll
        for (int i = 0; i < 4; i++) {
            float mt = fmaxf(fmaxf(s[i][0], s[i][1]), fmaxf(s[i][2], s[i][3]));
            mt = fmaxf(mt, __shfl_xor_sync(0xffffffffu, mt, 8));
            mt = fmaxf(mt, __shfl_xor_sync(0xffffffffu, mt, 4));
            mt = fmaxf(mt, __shfl_xor_sync(0xffffffffu, mt, 2));
            mt = fmaxf(mt, __shfl_xor_sync(0xffffffffu, mt, 1));
            float mnew = fmaxf(m_i[i], mt);
            float corr = __expf(m_i[i] - mnew);
            m_i[i] = mnew;
            float rs = 0.f;
            #pragma unroll
            for (int j = 0; j < 4; j++) {
                s[i][j] = __expf(s[i][j] - mnew);
                rs += s[i][j];
            }
            rs += __shfl_xor_sync(0xffffffffu, rs, 8);
            rs += __shfl_xor_sync(0xffffffffu, rs, 4);
            rs += __shfl_xor_sync(0xffffffffu, rs, 2);
            rs += __shfl_xor_sync(0xffffffffu, rs, 1);
            l_i[i] = l_i[i]*corr + rs;
            #pragma unroll
            for (int j = 0; j < 4; j++) {
                o[i][j] *= corr;
                Ss[(ty*4+i)*65 + tx*4 + j] = s[i][j];
            }
        }
        __syncthreads();

        // O += P V  (P broadcast across thread-row; V float4, conflict-free)
        #pragma unroll
        for (int kk = 0; kk < 64; kk++) {
            float p[4];
            #pragma unroll
            for (int i = 0; i < 4; i++) p[i] = Ss[(ty*4+i)*65 + kk];
            float4 vv = *(const float4*)&Vs[kk*64 + tx*4];
            #pragma unroll
            for (int i = 0; i < 4; i++) {
                o[i][0] += p[i]*vv.x;
                o[i][1] += p[i]*vv.y;
                o[i][2] += p[i]*vv.z;
                o[i][3] += p[i]*vv.w;
            }
        }
    }

    #pragma unroll
    for (int i = 0; i < 4; i++) {
        float inv = 1.0f / l_i[i];
        size_t off = ((size_t)b*TT + r0 + ty*4 + i)*HH + tx*4;
        *(float4*)&out[off] = make_float4(o[i][0]*inv, o[i][1]*inv,
                                          o[i][2]*inv, o[i][3]*inv);
    }
}

extern "C" void kernel_launch(void* const* d_in, const int* in_sizes, int n_in,
                              void* d_out, int out_size) {
    const float* x  = (const float*)d_in[0];
    const float* Wk = (const float*)d_in[1];
    const float* Wq = (const float*)d_in[2];
    const float* Wv = (const float*)d_in[3];
    float* out = (float*)d_out;

    proj_kernel<<<(BB*TT)/64, 256>>>(x, Wq, Wk, Wv);

    const int smem = (3*64*65 + 64*64) * (int)sizeof(float);  // 65792 B
    cudaFuncSetAttribute(attn_kernel,
                         cudaFuncAttributeMaxDynamicSharedMemorySize, smem);
    dim3 grid(TT/64, BB);
    attn_kernel<<<grid, 256, smem>>>(out);
}

// round 3
// speedup vs baseline: 2.5235x; 2.5235x over previous
#include <cuda_runtime.h>
#include <cuda_fp16.h>
#include <cstdint>

#define BB 8
#define TT 2048
#define CC 1024
#define HH 64

// hi/lo split halves of projected tensors (q pre-scaled by 1/sqrt(H))
__device__ __align__(16) __half g_qh[BB*TT*HH];
__device__ __align__(16) __half g_ql[BB*TT*HH];
__device__ __align__(16) __half g_kh[BB*TT*HH];
__device__ __align__(16) __half g_kl[BB*TT*HH];
__device__ __align__(16) __half g_vh[BB*TT*HH];

__device__ __forceinline__ uint32_t smaddr(const void* p) {
    return (uint32_t)__cvta_generic_to_shared(p);
}
__device__ __forceinline__ void ldsm4(uint32_t r[4], uint32_t a) {
    asm volatile("ldmatrix.sync.aligned.m8n8.x4.shared.b16 {%0,%1,%2,%3}, [%4];\n"
        : "=r"(r[0]), "=r"(r[1]), "=r"(r[2]), "=r"(r[3]) : "r"(a));
}
__device__ __forceinline__ void ldsm4t(uint32_t r[4], uint32_t a) {
    asm volatile("ldmatrix.sync.aligned.m8n8.x4.trans.shared.b16 {%0,%1,%2,%3}, [%4];\n"
        : "=r"(r[0]), "=r"(r[1]), "=r"(r[2]), "=r"(r[3]) : "r"(a));
}
__device__ __forceinline__ void mma16816(float d[4], const uint32_t a[4], const uint32_t b[2]) {
    asm volatile("mma.sync.aligned.m16n8k16.row.col.f32.f16.f16.f32 "
        "{%0,%1,%2,%3}, {%4,%5,%6,%7}, {%8,%9}, {%0,%1,%2,%3};\n"
        : "+f"(d[0]), "+f"(d[1]), "+f"(d[2]), "+f"(d[3])
        : "r"(a[0]), "r"(a[1]), "r"(a[2]), "r"(a[3]), "r"(b[0]), "r"(b[1]));
}
__device__ __forceinline__ uint32_t packh2(float a, float b) {
    __half2 h = __floats2half2_rn(a, b);
    return *reinterpret_cast<uint32_t*>(&h);
}

// ---------------------------------------------------------------------------
// Projection: [16384 x 1024] x [1024 x 192] with hi/lo fp16 split (3-mma).
// CTA: 128 threads / 4 warps, M-tile 64 (16 rows per warp), N = 192.
// ---------------------------------------------------------------------------
__global__ __launch_bounds__(128, 1) void proj_kernel(
    const float* __restrict__ x, const float* __restrict__ Wk,
    const float* __restrict__ Wq, const float* __restrict__ Wv)
{
    __shared__ __half xs[2][64][40];    // [prec][row][k], pad 32->40
    __shared__ __half ws[2][32][200];   // [prec][k][n=192], pad ->200

    const int tid = threadIdx.x;
    const int w = tid >> 5, lane = tid & 31;
    const int row0 = blockIdx.x * 64;
    const float* Wm[3] = {Wk, Wq, Wv};

    float acc[3][8][4];
    #pragma unroll
    for (int m = 0; m < 3; m++)
        #pragma unroll
        for (int nt = 0; nt < 8; nt++)
            #pragma unroll
            for (int e = 0; e < 4; e++) acc[m][nt][e] = 0.f;

    for (int k0 = 0; k0 < CC; k0 += 32) {
        __syncthreads();
        #pragma unroll
        for (int i = 0; i < 16; i++) {
            int idx = tid + i*128; int r = idx >> 5, c = idx & 31;
            float f = x[(size_t)(row0 + r)*CC + k0 + c];
            __half h = __float2half_rn(f);
            xs[0][r][c] = h;
            xs[1][r][c] = __float2half_rn(f - __half2float(h));
        }
        #pragma unroll
        for (int m = 0; m < 3; m++) {
            const float* W = Wm[m];
            #pragma unroll
            for (int i = 0; i < 16; i++) {
                int idx = tid + i*128; int r = idx >> 6, c = idx & 63;
                float f = W[(size_t)(k0 + r)*HH + c];
                __half h = __float2half_rn(f);
                ws[0][r][m*64 + c] = h;
                ws[1][r][m*64 + c] = __float2half_rn(f - __half2float(h));
            }
        }
        __syncthreads();

        #pragma unroll
        for (int sub = 0; sub < 2; sub++) {
            const int kk = sub*16;
            uint32_t ah[4], al[4];
            {
                int r = w*16 + (lane & 15);
                int c = kk + ((lane >> 4) << 3);
                ldsm4(ah, smaddr(&xs[0][r][c]));
                ldsm4(al, smaddr(&xs[1][r][c]));
            }
            #pragma unroll
            for (int m = 0; m < 3; m++) {
                #pragma unroll
                for (int jj = 0; jj < 4; jj++) {
                    int g = lane >> 3, rl = lane & 7;
                    int r = kk + (g & 1)*8 + rl;
                    int c = m*64 + jj*16 + (g >> 1)*8;
                    uint32_t bh[4], bl[4];
                    ldsm4t(bh, smaddr(&ws[0][r][c]));
                    ldsm4t(bl, smaddr(&ws[1][r][c]));
                    mma16816(acc[m][2*jj],   ah, bh);
                    mma16816(acc[m][2*jj],   ah, bl);
                    mma16816(acc[m][2*jj],   al, bh);
                    mma16816(acc[m][2*jj+1], ah, bh + 2);
                    mma16816(acc[m][2*jj+1], ah, bl + 2);
                    mma16816(acc[m][2*jj+1], al, bh + 2);
                }
            }
        }
    }

    // epilogue: split-store k, q (pre-scaled), v
    const int rl = lane >> 2, q2 = (lane & 3)*2;
    #pragma unroll
    for (int er = 0; er < 2; er++) {
        size_t r = (size_t)(row0 + w*16 + rl + er*8);
        #pragma unroll
        for (int nt = 0; nt < 8; nt++) {
            size_t off = r*HH + nt*8 + q2;
            {   // k
                float v0 = acc[0][nt][er*2], v1 = acc[0][nt][er*2+1];
                __half h0 = __float2half_rn(v0), h1 = __float2half_rn(v1);
                *(__half2*)&g_kh[off] = __halves2half2(h0, h1);
                *(__half2*)&g_kl[off] = __halves2half2(
                    __float2half_rn(v0 - __half2float(h0)),
                    __float2half_rn(v1 - __half2float(h1)));
            }
            {   // q, pre-scaled by 1/sqrt(64)
                float v0 = acc[1][nt][er*2]*0.125f, v1 = acc[1][nt][er*2+1]*0.125f;
                __half h0 = __float2half_rn(v0), h1 = __float2half_rn(v1);
                *(__half2*)&g_qh[off] = __halves2half2(h0, h1);
                *(__half2*)&g_ql[off] = __halves2half2(
                    __float2half_rn(v0 - __half2float(h0)),
                    __float2half_rn(v1 - __half2float(h1)));
            }
            {   // v
                *(__half2*)&g_vh[off] =
                    __floats2half2_rn(acc[2][nt][er*2], acc[2][nt][er*2+1]);
            }
        }
    }
}

// ---------------------------------------------------------------------------
// Flash attention, fp16 mma: Br=Bc=64, 4 warps. QK^T uses hi/lo 3-mma; P is
// reused in-register as the A fragment of PV (accum layout == A layout).
// ---------------------------------------------------------------------------
__global__ __launch_bounds__(128, 1) void attn_kernel(float* __restrict__ out)
{
    __shared__ __half Qs[2][64][72];
    __shared__ __half Ks[2][64][72];
    __shared__ __half Vs[64][72];

    const int tid = threadIdx.x;
    const int w = tid >> 5, lane = tid & 31;
    const int qt = (int)gridDim.x - 1 - (int)blockIdx.x;  // big tiles first
    const int b = blockIdx.y;

    {   // load Q tiles (contiguous 64x64 half block)
        const __half* qh = g_qh + ((size_t)b*TT + qt*64)*HH;
        const __half* ql = g_ql + ((size_t)b*TT + qt*64)*HH;
        #pragma unroll
        for (int i = 0; i < 4; i++) {
            int idx = tid + i*128; int r = idx >> 3, c = (idx & 7)*8;
            *(int4*)&Qs[0][r][c] = *(const int4*)&qh[r*64 + c];
            *(int4*)&Qs[1][r][c] = *(const int4*)&ql[r*64 + c];
        }
    }
    __syncthreads();

    uint32_t aqh[4][4], aql[4][4];
    #pragma unroll
    for (int kc = 0; kc < 4; kc++) {
        int r = w*16 + (lane & 15), c = kc*16 + ((lane >> 4) << 3);
        ldsm4(aqh[kc], smaddr(&Qs[0][r][c]));
        ldsm4(aql[kc], smaddr(&Qs[1][r][c]));
    }

    float o[8][4];
    #pragma unroll
    for (int nt = 0; nt < 8; nt++)
        #pragma unroll
        for (int e = 0; e < 4; e++) o[nt][e] = 0.f;
    float m0 = -1e9f, m1 = -1e9f, l0 = 0.f, l1 = 0.f;

    for (int kt = 0; kt <= qt; kt++) {
        __syncthreads();
        {
            const size_t base = ((size_t)b*TT + kt*64)*HH;
            const __half* kh = g_kh + base;
            const __half* kl = g_kl + base;
            const __half* vh = g_vh + base;
            #pragma unroll
            for (int i = 0; i < 4; i++) {
                int idx = tid + i*128; int r = idx >> 3, c = (idx & 7)*8;
                *(int4*)&Ks[0][r][c] = *(const int4*)&kh[r*64 + c];
                *(int4*)&Ks[1][r][c] = *(const int4*)&kl[r*64 + c];
                *(int4*)&Vs[r][c]    = *(const int4*)&vh[r*64 + c];
            }
        }
        __syncthreads();

        // S = Q K^T (compensated)
        float s[8][4];
        #pragma unroll
        for (int nt = 0; nt < 8; nt++)
            #pragma unroll
            for (int e = 0; e < 4; e++) s[nt][e] = 0.f;
        #pragma unroll
        for (int kc = 0; kc < 4; kc++) {
            #pragma unroll
            for (int jj = 0; jj < 4; jj++) {
                int g = lane >> 3, rl = lane & 7;
                int r = jj*16 + (g >> 1)*8 + rl;
                int c = kc*16 + (g & 1)*8;
                uint32_t bh[4], bl[4];
                ldsm4(bh, smaddr(&Ks[0][r][c]));
                ldsm4(bl, smaddr(&Ks[1][r][c]));
                mma16816(s[2*jj],   aqh[kc], bh);
                mma16816(s[2*jj],   aqh[kc], bl);
                mma16816(s[2*jj],   aql[kc], bh);
                mma16816(s[2*jj+1], aqh[kc], bh + 2);
                mma16816(s[2*jj+1], aqh[kc], bl + 2);
                mma16816(s[2*jj+1], aql[kc], bh + 2);
            }
        }

        if (kt == qt) {   // causal mask on diagonal tile
            int r0l = w*16 + (lane >> 2);
            int c0l = (lane & 3)*2;
            #pragma unroll
            for (int nt = 0; nt < 8; nt++) {
                int c = nt*8 + c0l;
                if (c     > r0l)     s[nt][0] = -1e9f;
                if (c + 1 > r0l)     s[nt][1] = -1e9f;
                if (c     > r0l + 8) s[nt][2] = -1e9f;
                if (c + 1 > r0l + 8) s[nt][3] = -1e9f;
            }
        }

        // online softmax (rows r = w*16 + lane/4 and +8)
        float rm0 = -1e9f, rm1 = -1e9f;
        #pragma unroll
        for (int nt = 0; nt < 8; nt++) {
            rm0 = fmaxf(rm0, fmaxf(s[nt][0], s[nt][1]));
            rm1 = fmaxf(rm1, fmaxf(s[nt][2], s[nt][3]));
        }
        rm0 = fmaxf(rm0, __shfl_xor_sync(0xffffffffu, rm0, 1));
        rm0 = fmaxf(rm0, __shfl_xor_sync(0xffffffffu, rm0, 2));
        rm1 = fmaxf(rm1, __shfl_xor_sync(0xffffffffu, rm1, 1));
        rm1 = fmaxf(rm1, __shfl_xor_sync(0xffffffffu, rm1, 2));
        float mn0 = fmaxf(m0, rm0), mn1 = fmaxf(m1, rm1);
        float corr0 = __expf(m0 - mn0), corr1 = __expf(m1 - mn1);
        m0 = mn0; m1 = mn1;
        float rs0 = 0.f, rs1 = 0.f;
        #pragma unroll
        for (int nt = 0; nt < 8; nt++) {
            s[nt][0] = __expf(s[nt][0] - mn0); rs0 += s[nt][0];
            s[nt][1] = __expf(s[nt][1] - mn0); rs0 += s[nt][1];
            s[nt][2] = __expf(s[nt][2] - mn1); rs1 += s[nt][2];
            s[nt][3] = __expf(s[nt][3] - mn1); rs1 += s[nt][3];
        }
        rs0 += __shfl_xor_sync(0xffffffffu, rs0, 1);
        rs0 += __shfl_xor_sync(0xffffffffu, rs0, 2);
        rs1 += __shfl_xor_sync(0xffffffffu, rs1, 1);
        rs1 += __shfl_xor_sync(0xffffffffu, rs1, 2);
        l0 = l0*corr0 + rs0;
        l1 = l1*corr1 + rs1;
        #pragma unroll
        for (int nt = 0; nt < 8; nt++) {
            o[nt][0] *= corr0; o[nt][1] *= corr0;
            o[nt][2] *= corr1; o[nt][3] *= corr1;
        }

        // O += P V  (P accum regs reinterpreted as A fragments)
        #pragma unroll
        for (int kc = 0; kc < 4; kc++) {
            uint32_t ap[4];
            ap[0] = packh2(s[2*kc][0],   s[2*kc][1]);
            ap[1] = packh2(s[2*kc][2],   s[2*kc][3]);
            ap[2] = packh2(s[2*kc+1][0], s[2*kc+1][1]);
            ap[3] = packh2(s[2*kc+1][2], s[2*kc+1][3]);
            #pragma unroll
            for (int jj = 0; jj < 4; jj++) {
                int g = lane >> 3, rl = lane & 7;
                int r = kc*16 + (g & 1)*8 + rl;
                int c = jj*16 + (g >> 1)*8;
                uint32_t vb[4];
                ldsm4t(vb, smaddr(&Vs[r][c]));
                mma16816(o[2*jj],   ap, vb);
                mma16816(o[2*jj+1], ap, vb + 2);
            }
        }
    }

    const float inv0 = 1.0f/l0, inv1 = 1.0f/l1;
    const size_t rg = ((size_t)b*TT + qt*64 + w*16 + (lane >> 2))*HH;
    #pragma unroll
    for (int nt = 0; nt < 8; nt++) {
        int c = nt*8 + (lane & 3)*2;
        *(float2*)&out[rg + c] = make_float2(o[nt][0]*inv0, o[nt][1]*inv0);
        *(float2*)&out[rg + 8*HH + c] = make_float2(o[nt][2]*inv1, o[nt][3]*inv1);
    }
}

extern "C" void kernel_launch(void* const* d_in, const int* in_sizes, int n_in,
                              void* d_out, int out_size) {
    const float* x  = (const float*)d_in[0];
    const float* Wk = (const float*)d_in[1];
    const float* Wq = (const float*)d_in[2];
    const float* Wv = (const float*)d_in[3];
    float* out = (float*)d_out;

    proj_kernel<<<(BB*TT)/64, 128>>>(x, Wk, Wq, Wv);
    attn_kernel<<<dim3(TT/64, BB), 128>>>(out);
}

// round 4
// speedup vs baseline: 2.5282x; 1.0019x over previous
#include <cuda_runtime.h>
#include <cuda_fp16.h>
#include <cstdint>

#define BB 8
#define TT 2048
#define CC 1024
#define HH 64

// hi/lo split halves of projected tensors (q pre-scaled by 1/sqrt(H))
__device__ __align__(16) __half g_qh[BB*TT*HH];
__device__ __align__(16) __half g_ql[BB*TT*HH];
__device__ __align__(16) __half g_kh[BB*TT*HH];
__device__ __align__(16) __half g_kl[BB*TT*HH];
__device__ __align__(16) __half g_vh[BB*TT*HH];

__device__ __forceinline__ uint32_t smaddr(const void* p) {
    return (uint32_t)__cvta_generic_to_shared(p);
}
__device__ __forceinline__ void ldsm4(uint32_t r[4], uint32_t a) {
    asm volatile("ldmatrix.sync.aligned.m8n8.x4.shared.b16 {%0,%1,%2,%3}, [%4];\n"
        : "=r"(r[0]), "=r"(r[1]), "=r"(r[2]), "=r"(r[3]) : "r"(a));
}
__device__ __forceinline__ void ldsm4t(uint32_t r[4], uint32_t a) {
    asm volatile("ldmatrix.sync.aligned.m8n8.x4.trans.shared.b16 {%0,%1,%2,%3}, [%4];\n"
        : "=r"(r[0]), "=r"(r[1]), "=r"(r[2]), "=r"(r[3]) : "r"(a));
}
__device__ __forceinline__ void mma16816(float d[4], const uint32_t a[4], const uint32_t b[2]) {
    asm volatile("mma.sync.aligned.m16n8k16.row.col.f32.f16.f16.f32 "
        "{%0,%1,%2,%3}, {%4,%5,%6,%7}, {%8,%9}, {%0,%1,%2,%3};\n"
        : "+f"(d[0]), "+f"(d[1]), "+f"(d[2]), "+f"(d[3])
        : "r"(a[0]), "r"(a[1]), "r"(a[2]), "r"(a[3]), "r"(b[0]), "r"(b[1]));
}
__device__ __forceinline__ uint32_t packh2(float a, float b) {
    __half2 h = __floats2half2_rn(a, b);
    return *reinterpret_cast<uint32_t*>(&h);
}

// ---------------------------------------------------------------------------
// Projection: [16384 x 1024] x [1024 x 192] with hi/lo fp16 split (3-mma).
// CTA: 128 threads / 4 warps, M-tile 64 (16 rows per warp), N = 192.
// ---------------------------------------------------------------------------
__global__ __launch_bounds__(128, 1) void proj_kernel(
    const float* __restrict__ x, const float* __restrict__ Wk,
    const float* __restrict__ Wq, const float* __restrict__ Wv)
{
    __shared__ __half xs[2][64][40];    // [prec][row][k], pad 32->40
    __shared__ __half ws[2][32][200];   // [prec][k][n=192], pad ->200

    const int tid = threadIdx.x;
    const int w = tid >> 5, lane = tid & 31;
    const int row0 = blockIdx.x * 64;
    const float* Wm[3] = {Wk, Wq, Wv};

    float acc[3][8][4];
    #pragma unroll
    for (int m = 0; m < 3; m++)
        #pragma unroll
        for (int nt = 0; nt < 8; nt++)
            #pragma unroll
            for (int e = 0; e < 4; e++) acc[m][nt][e] = 0.f;

    for (int k0 = 0; k0 < CC; k0 += 32) {
        __syncthreads();
        #pragma unroll
        for (int i = 0; i < 16; i++) {
            int idx = tid + i*128; int r = idx >> 5, c = idx & 31;
            float f = x[(size_t)(row0 + r)*CC + k0 + c];
            __half h = __float2half_rn(f);
            xs[0][r][c] = h;
            xs[1][r][c] = __float2half_rn(f - __half2float(h));
        }
        #pragma unroll
        for (int m = 0; m < 3; m++) {
            const float* W = Wm[m];
            #pragma unroll
            for (int i = 0; i < 16; i++) {
                int idx = tid + i*128; int r = idx >> 6, c = idx & 63;
                float f = W[(size_t)(k0 + r)*HH + c];
                __half h = __float2half_rn(f);
                ws[0][r][m*64 + c] = h;
                ws[1][r][m*64 + c] = __float2half_rn(f - __half2float(h));
            }
        }
        __syncthreads();

        #pragma unroll
        for (int sub = 0; sub < 2; sub++) {
            const int kk = sub*16;
            uint32_t ah[4], al[4];
            {
                int r = w*16 + (lane & 15);
                int c = kk + ((lane >> 4) << 3);
                ldsm4(ah, smaddr(&xs[0][r][c]));
                ldsm4(al, smaddr(&xs[1][r][c]));
            }
            #pragma unroll
            for (int m = 0; m < 3; m++) {
                #pragma unroll
                for (int jj = 0; jj < 4; jj++) {
                    int g = lane >> 3, rl = lane & 7;
                    int r = kk + (g & 1)*8 + rl;
                    int c = m*64 + jj*16 + (g >> 1)*8;
                    uint32_t bh[4], bl[4];
                    ldsm4t(bh, smaddr(&ws[0][r][c]));
                    ldsm4t(bl, smaddr(&ws[1][r][c]));
                    mma16816(acc[m][2*jj],   ah, bh);
                    mma16816(acc[m][2*jj],   ah, bl);
                    mma16816(acc[m][2*jj],   al, bh);
                    mma16816(acc[m][2*jj+1], ah, bh + 2);
                    mma16816(acc[m][2*jj+1], ah, bl + 2);
                    mma16816(acc[m][2*jj+1], al, bh + 2);
                }
            }
        }
    }

    // epilogue: split-store k, q (pre-scaled), v
    const int rl = lane >> 2, q2 = (lane & 3)*2;
    #pragma unroll
    for (int er = 0; er < 2; er++) {
        size_t r = (size_t)(row0 + w*16 + rl + er*8);
        #pragma unroll
        for (int nt = 0; nt < 8; nt++) {
            size_t off = r*HH + nt*8 + q2;
            {   // k
                float v0 = acc[0][nt][er*2], v1 = acc[0][nt][er*2+1];
                __half h0 = __float2half_rn(v0), h1 = __float2half_rn(v1);
                *(__half2*)&g_kh[off] = __halves2half2(h0, h1);
                *(__half2*)&g_kl[off] = __halves2half2(
                    __float2half_rn(v0 - __half2float(h0)),
                    __float2half_rn(v1 - __half2float(h1)));
            }
            {   // q, pre-scaled by 1/sqrt(64)
                float v0 = acc[1][nt][er*2]*0.125f, v1 = acc[1][nt][er*2+1]*0.125f;
                __half h0 = __float2half_rn(v0), h1 = __float2half_rn(v1);
                *(__half2*)&g_qh[off] = __halves2half2(h0, h1);
                *(__half2*)&g_ql[off] = __halves2half2(
                    __float2half_rn(v0 - __half2float(h0)),
                    __float2half_rn(v1 - __half2float(h1)));
            }
            {   // v
                *(__half2*)&g_vh[off] =
                    __floats2half2_rn(acc[2][nt][er*2], acc[2][nt][er*2+1]);
            }
        }
    }
}

// ---------------------------------------------------------------------------
// Flash attention, fp16 mma: Br=Bc=64, 4 warps. QK^T uses hi/lo 3-mma; P is
// reused in-register as the A fragment of PV (accum layout == A layout).
// ---------------------------------------------------------------------------
__global__ __launch_bounds__(128, 1) void attn_kernel(float* __restrict__ out)
{
    __shared__ __half Qs[2][64][72];
    __shared__ __half Ks[2][64][72];
    __shared__ __half Vs[64][72];

    const int tid = threadIdx.x;
    const int w = tid >> 5, lane = tid & 31;
    const int qt = (int)gridDim.x - 1 - (int)blockIdx.x;  // big tiles first
    const int b = blockIdx.y;

    {   // load Q tiles (contiguous 64x64 half block)
        const __half* qh = g_qh + ((size_t)b*TT + qt*64)*HH;
        const __half* ql = g_ql + ((size_t)b*TT + qt*64)*HH;
        #pragma unroll
        for (int i = 0; i < 4; i++) {
            int idx = tid + i*128; int r = idx >> 3, c = (idx & 7)*8;
            *(int4*)&Qs[0][r][c] = *(const int4*)&qh[r*64 + c];
            *(int4*)&Qs[1][r][c] = *(const int4*)&ql[r*64 + c];
        }
    }
    __syncthreads();

    uint32_t aqh[4][4], aql[4][4];
    #pragma unroll
    for (int kc = 0; kc < 4; kc++) {
        int r = w*16 + (lane & 15), c = kc*16 + ((lane >> 4) << 3);
        ldsm4(aqh[kc], smaddr(&Qs[0][r][c]));
        ldsm4(aql[kc], smaddr(&Qs[1][r][c]));
    }

    float o[8][4];
    #pragma unroll
    for (int nt = 0; nt < 8; nt++)
        #pragma unroll
        for (int e = 0; e < 4; e++) o[nt][e] = 0.f;
    float m0 = -1e9f, m1 = -1e9f, l0 = 0.f, l1 = 0.f;

    for (int kt = 0; kt <= qt; kt++) {
        __syncthreads();
        {
            const size_t base = ((size_t)b*TT + kt*64)*HH;
            const __half* kh = g_kh + base;
            const __half* kl = g_kl + base;
            const __half* vh = g_vh + base;
            #pragma unroll
            for (int i = 0; i < 4; i++) {
                int idx = tid + i*128; int r = idx >> 3, c = (idx & 7)*8;
                *(int4*)&Ks[0][r][c] = *(const int4*)&kh[r*64 + c];
                *(int4*)&Ks[1][r][c] = *(const int4*)&kl[r*64 + c];
                *(int4*)&Vs[r][c]    = *(const int4*)&vh[r*64 + c];
            }
        }
        __syncthreads();

        // S = Q K^T (compensated)
        float s[8][4];
        #pragma unroll
        for (int nt = 0; nt < 8; nt++)
            #pragma unroll
            for (int e = 0; e < 4; e++) s[nt][e] = 0.f;
        #pragma unroll
        for (int kc = 0; kc < 4; kc++) {
            #pragma unroll
            for (int jj = 0; jj < 4; jj++) {
                int g = lane >> 3, rl = lane & 7;
                int r = jj*16 + (g >> 1)*8 + rl;
                int c = kc*16 + (g & 1)*8;
                uint32_t bh[4], bl[4];
                ldsm4(bh, smaddr(&Ks[0][r][c]));
                ldsm4(bl, smaddr(&Ks[1][r][c]));
                mma16816(s[2*jj],   aqh[kc], bh);
                mma16816(s[2*jj],   aqh[kc], bl);
                mma16816(s[2*jj],   aql[kc], bh);
                mma16816(s[2*jj+1], aqh[kc], bh + 2);
                mma16816(s[2*jj+1], aqh[kc], bl + 2);
                mma16816(s[2*jj+1], aql[kc], bh + 2);
            }
        }

        if (kt == qt) {   // causal mask on diagonal tile
            int r0l = w*16 + (lane >> 2);
            int c0l = (lane & 3)*2;
            #pragma unroll
            for (int nt = 0; nt < 8; nt++) {
                int c = nt*8 + c0l;
                if (c     > r0l)     s[nt][0] = -1e9f;
                if (c + 1 > r0l)     s[nt][1] = -1e9f;
                if (c     > r0l + 8) s[nt][2] = -1e9f;
                if (c + 1 > r0l + 8) s[nt][3] = -1e9f;
            }
        }

        // online softmax (rows r = w*16 + lane/4 and +8)
        float rm0 = -1e9f, rm1 = -1e9f;
        #pragma unroll
        for (int nt = 0; nt < 8; nt++) {
            rm0 = fmaxf(rm0, fmaxf(s[nt][0], s[nt][1]));
            rm1 = fmaxf(rm1, fmaxf(s[nt][2], s[nt][3]));
        }
        rm0 = fmaxf(rm0, __shfl_xor_sync(0xffffffffu, rm0, 1));
        rm0 = fmaxf(rm0, __shfl_xor_sync(0xffffffffu, rm0, 2));
        rm1 = fmaxf(rm1, __shfl_xor_sync(0xffffffffu, rm1, 1));
        rm1 = fmaxf(rm1, __shfl_xor_sync(0xffffffffu, rm1, 2));
        float mn0 = fmaxf(m0, rm0), mn1 = fmaxf(m1, rm1);
        float corr0 = __expf(m0 - mn0), corr1 = __expf(m1 - mn1);
        m0 = mn0; m1 = mn1;
        float rs0 = 0.f, rs1 = 0.f;
        #pragma unroll
        for (int nt = 0; nt < 8; nt++) {
            s[nt][0] = __expf(s[nt][0] - mn0); rs0 += s[nt][0];
            s[nt][1] = __expf(s[nt][1] - mn0); rs0 += s[nt][1];
            s[nt][2] = __expf(s[nt][2] - mn1); rs1 += s[nt][2];
            s[nt][3] = __expf(s[nt][3] - mn1); rs1 += s[nt][3];
        }
        rs0 += __shfl_xor_sync(0xffffffffu, rs0, 1);
        rs0 += __shfl_xor_sync(0xffffffffu, rs0, 2);
        rs1 += __shfl_xor_sync(0xffffffffu, rs1, 1);
        rs1 += __shfl_xor_sync(0xffffffffu, rs1, 2);
        l0 = l0*corr0 + rs0;
        l1 = l1*corr1 + rs1;
        #pragma unroll
        for (int nt = 0; nt < 8; nt++) {
            o[nt][0] *= corr0; o[nt][1] *= corr0;
            o[nt][2] *= corr1; o[nt][3] *= corr1;
        }

        // O += P V  (P accum regs reinterpreted as A fragments)
        #pragma unroll
        for (int kc = 0; kc < 4; kc++) {
            uint32_t ap[4];
            ap[0] = packh2(s[2*kc][0],   s[2*kc][1]);
            ap[1] = packh2(s[2*kc][2],   s[2*kc][3]);
            ap[2] = packh2(s[2*kc+1][0], s[2*kc+1][1]);
            ap[3] = packh2(s[2*kc+1][2], s[2*kc+1][3]);
            #pragma unroll
            for (int jj = 0; jj < 4; jj++) {
                int g = lane >> 3, rl = lane & 7;
                int r = kc*16 + (g & 1)*8 + rl;
                int c = jj*16 + (g >> 1)*8;
                uint32_t vb[4];
                ldsm4t(vb, smaddr(&Vs[r][c]));
                mma16816(o[2*jj],   ap, vb);
                mma16816(o[2*jj+1], ap, vb + 2);
            }
        }
    }

    const float inv0 = 1.0f/l0, inv1 = 1.0f/l1;
    const size_t rg = ((size_t)b*TT + qt*64 + w*16 + (lane >> 2))*HH;
    #pragma unroll
    for (int nt = 0; nt < 8; nt++) {
        int c = nt*8 + (lane & 3)*2;
        *(float2*)&out[rg + c] = make_float2(o[nt][0]*inv0, o[nt][1]*inv0);
        *(float2*)&out[rg + 8*HH + c] = make_float2(o[nt][2]*inv1, o[nt][3]*inv1);
    }
}

extern "C" void kernel_launch(void* const* d_in, const int* in_sizes, int n_in,
                              void* d_out, int out_size) {
    const float* x  = (const float*)d_in[0];
    const float* Wk = (const float*)d_in[1];
    const float* Wq = (const float*)d_in[2];
    const float* Wv = (const float*)d_in[3];
    float* out = (float*)d_out;

    proj_kernel<<<(BB*TT)/64, 128>>>(x, Wk, Wq, Wv);
    attn_kernel<<<dim3(TT/64, BB), 128>>>(out);
}

// round 5
// speedup vs baseline: 3.5865x; 1.4186x over previous
#include <cuda_runtime.h>
#include <cuda_fp16.h>
#include <cstdint>

#define BB 8
#define TT 2048
#define CC 1024
#define HH 64

// projected tensors: q hi/lo (pre-scaled by 1/8), k hi only, v hi only
__device__ __align__(16) __half g_qh[BB*TT*HH];
__device__ __align__(16) __half g_ql[BB*TT*HH];
__device__ __align__(16) __half g_kh[BB*TT*HH];
__device__ __align__(16) __half g_vh[BB*TT*HH];

__device__ __forceinline__ uint32_t smaddr(const void* p) {
    return (uint32_t)__cvta_generic_to_shared(p);
}
__device__ __forceinline__ void ldsm4(uint32_t r[4], uint32_t a) {
    asm volatile("ldmatrix.sync.aligned.m8n8.x4.shared.b16 {%0,%1,%2,%3}, [%4];\n"
        : "=r"(r[0]), "=r"(r[1]), "=r"(r[2]), "=r"(r[3]) : "r"(a));
}
__device__ __forceinline__ void ldsm4t(uint32_t r[4], uint32_t a) {
    asm volatile("ldmatrix.sync.aligned.m8n8.x4.trans.shared.b16 {%0,%1,%2,%3}, [%4];\n"
        : "=r"(r[0]), "=r"(r[1]), "=r"(r[2]), "=r"(r[3]) : "r"(a));
}
__device__ __forceinline__ void mma16816(float d[4], const uint32_t a[4], const uint32_t b[2]) {
    asm volatile("mma.sync.aligned.m16n8k16.row.col.f32.f16.f16.f32 "
        "{%0,%1,%2,%3}, {%4,%5,%6,%7}, {%8,%9}, {%0,%1,%2,%3};\n"
        : "+f"(d[0]), "+f"(d[1]), "+f"(d[2]), "+f"(d[3])
        : "r"(a[0]), "r"(a[1]), "r"(a[2]), "r"(a[3]), "r"(b[0]), "r"(b[1]));
}
__device__ __forceinline__ uint32_t packh2(float a, float b) {
    __half2 h = __floats2half2_rn(a, b);
    return *reinterpret_cast<uint32_t*>(&h);
}

// ---------------------------------------------------------------------------
// Projection: [16384 x 1024] x [1024 x 192] (cols = K|Q|V).
// 256 threads / 8 warps. Warp-group wg (= wid/4) owns a 96-col slice; warp
// w4 (= wid%4) owns 16 rows. x is fp16 hi/lo 2-term compensated; W single fp16.
// ---------------------------------------------------------------------------
__global__ __launch_bounds__(256, 2) void proj_kernel(
    const float* __restrict__ x, const float* __restrict__ Wk,
    const float* __restrict__ Wq, const float* __restrict__ Wv)
{
    __shared__ __half xs[2][64][40];     // [prec][row][k] pad 32->40
    __shared__ __half ws[32][200];       // [k][n=192] pad ->200

    const int tid = threadIdx.x;
    const int wid = tid >> 5, lane = tid & 31;
    const int wg = wid >> 2, w4 = wid & 3;
    const int row0 = blockIdx.x * 64;
    const float* Wm[3] = {Wk, Wq, Wv};

    float acc[12][4];
    #pragma unroll
    for (int j = 0; j < 12; j++)
        #pragma unroll
        for (int e = 0; e < 4; e++) acc[j][e] = 0.f;

    #pragma unroll 1
    for (int k0 = 0; k0 < CC; k0 += 32) {
        __syncthreads();
        #pragma unroll
        for (int i = 0; i < 8; i++) {              // x: 64x32 fp32
            int idx = tid + i*256; int r = idx >> 5, c = idx & 31;
            float f = __ldg(&x[(size_t)(row0 + r)*CC + k0 + c]);
            __half h = __float2half_rn(f);
            xs[0][r][c] = h;
            xs[1][r][c] = __float2half_rn(f - __half2float(h));
        }
        #pragma unroll
        for (int m = 0; m < 3; m++) {              // W: 32x64 fp32 each
            #pragma unroll
            for (int i = 0; i < 8; i++) {
                int idx = tid + i*256; int r = idx >> 6, c = idx & 63;
                ws[r][m*64 + c] =
                    __float2half_rn(__ldg(&Wm[m][(size_t)(k0 + r)*HH + c]));
            }
        }
        __syncthreads();

        #pragma unroll
        for (int sub = 0; sub < 2; sub++) {
            uint32_t ah[4], al[4];
            int ar = w4*16 + (lane & 15), ac = sub*16 + ((lane >> 4) << 3);
            ldsm4(ah, smaddr(&xs[0][ar][ac]));
            ldsm4(al, smaddr(&xs[1][ar][ac]));
            int g = lane >> 3, rl = lane & 7;
            int br = sub*16 + (g & 1)*8 + rl;
            #pragma unroll
            for (int j = 0; j < 6; j++) {
                int bc = wg*96 + j*16 + (g >> 1)*8;
                uint32_t bh[4];
                ldsm4t(bh, smaddr(&ws[br][bc]));
                mma16816(acc[2*j],   ah, bh);
                mma16816(acc[2*j],   al, bh);
                mma16816(acc[2*j+1], ah, bh + 2);
                mma16816(acc[2*j+1], al, bh + 2);
            }
        }
    }

    // epilogue
    const int rl = lane >> 2, q2 = (lane & 3)*2;
    #pragma unroll
    for (int j = 0; j < 6; j++) {
        #pragma unroll
        for (int h = 0; h < 2; h++) {
            int n = wg*96 + j*16 + h*8 + q2;       // even col of the pair
            int m = n >> 6, hc = n & 63;
            #pragma unroll
            for (int er = 0; er < 2; er++) {
                float v0 = acc[2*j+h][er*2], v1 = acc[2*j+h][er*2+1];
                size_t off = (size_t)(row0 + w4*16 + rl + er*8)*HH + hc;
                if (m == 2) {
                    *(__half2*)&g_vh[off] = __floats2half2_rn(v0, v1);
                } else if (m == 0) {
                    *(__half2*)&g_kh[off] = __floats2half2_rn(v0, v1);
                } else {
                    v0 *= 0.125f; v1 *= 0.125f;
                    __half h0 = __float2half_rn(v0), h1 = __float2half_rn(v1);
                    *(__half2*)&g_qh[off] = __halves2half2(h0, h1);
                    *(__half2*)&g_ql[off] = __halves2half2(
                        __float2half_rn(v0 - __half2float(h0)),
                        __float2half_rn(v1 - __half2float(h1)));
                }
            }
        }
    }
}

// ---------------------------------------------------------------------------
// Flash attention: Br=Bc=64, 4 warps, cp.async double-buffered K/V.
// QK^T 2-term compensated (q hi/lo x k); PV single fp16.
// smem (halfs): Qh[64][72] @0, Ql @4608, buf b: Kh @9216+b*9216... (see offs)
// ---------------------------------------------------------------------------
#define ATT_SMEM_BYTES ((4608*2 + 2*9216) * 2)    // 55296

__device__ __forceinline__ void kv_prefetch(__half* sh, int buf, size_t gbase,
                                            int tid)
{
    __half* base = sh + 9216 + buf*9216;
    #pragma unroll
    for (int i = 0; i < 8; i++) {
        int j = tid + i*128;               // 0..1023
        int surf = j >> 9;                 // 0=K, 1=V
        int rc = j & 511;
        int r = rc >> 3, c = (rc & 7)*8;
        const __half* src = (surf ? g_vh : g_kh) + gbase + r*64 + c;
        uint32_t dst = smaddr(base + surf*4608 + r*72 + c);
        asm volatile("cp.async.cg.shared.global [%0], [%1], 16;"
                     :: "r"(dst), "l"(src));
    }
}

__global__ __launch_bounds__(128) void attn_kernel(float* __restrict__ out)
{
    extern __shared__ __half sh[];
    __half* Qh = sh;
    __half* Ql = sh + 4608;

    const int tid = threadIdx.x;
    const int w = tid >> 5, lane = tid & 31;
    const int qt = (int)gridDim.x - 1 - (int)blockIdx.x;   // big tiles first
    const int b = blockIdx.y;
    const size_t kvb = (size_t)b*TT*HH;

    kv_prefetch(sh, 0, kvb, tid);
    asm volatile("cp.async.commit_group;");

    {   // Q tiles
        const size_t qb = kvb + (size_t)qt*64*HH;
        #pragma unroll
        for (int i = 0; i < 4; i++) {
            int idx = tid + i*128; int r = idx >> 3, c = (idx & 7)*8;
            *(int4*)&Qh[r*72 + c] = *(const int4*)&g_qh[qb + r*64 + c];
            *(int4*)&Ql[r*72 + c] = *(const int4*)&g_ql[qb + r*64 + c];
        }
    }
    __syncthreads();

    uint32_t aqh[4][4], aql[4][4];
    #pragma unroll
    for (int kc = 0; kc < 4; kc++) {
        int r = w*16 + (lane & 15), c = kc*16 + ((lane >> 4) << 3);
        ldsm4(aqh[kc], smaddr(&Qh[r*72 + c]));
        ldsm4(aql[kc], smaddr(&Ql[r*72 + c]));
    }

    float o[8][4];
    #pragma unroll
    for (int nt = 0; nt < 8; nt++)
        #pragma unroll
        for (int e = 0; e < 4; e++) o[nt][e] = 0.f;
    float m0 = -1e9f, m1 = -1e9f, l0 = 0.f, l1 = 0.f;

    #pragma unroll 1
    for (int kt = 0; kt <= qt; kt++) {
        __syncthreads();    // everyone done reading the buffer we re-fill next
        if (kt < qt) {
            kv_prefetch(sh, (kt+1) & 1, kvb + (size_t)(kt+1)*64*HH, tid);
            asm volatile("cp.async.commit_group;");
            asm volatile("cp.async.wait_group 1;");
        } else {
            asm volatile("cp.async.wait_group 0;");
        }
        __syncthreads();

        __half* Khp = sh + 9216 + (kt & 1)*9216;
        __half* Vsp = Khp + 4608;

        // S = Q K^T (2-term compensated)
        float s[8][4];
        #pragma unroll
        for (int nt = 0; nt < 8; nt++)
            #pragma unroll
            for (int e = 0; e < 4; e++) s[nt][e] = 0.f;
        const int g = lane >> 3, rl8 = lane & 7;
        #pragma unroll
        for (int kc = 0; kc < 4; kc++) {
            #pragma unroll
            for (int jj = 0; jj < 4; jj++) {
                int r = jj*16 + (g >> 1)*8 + rl8;
                int ccol = kc*16 + (g & 1)*8;
                uint32_t bh[4];
                ldsm4(bh, smaddr(&Khp[r*72 + ccol]));
                mma16816(s[2*jj],   aqh[kc], bh);
                mma16816(s[2*jj],   aql[kc], bh);
                mma16816(s[2*jj+1], aqh[kc], bh + 2);
                mma16816(s[2*jj+1], aql[kc], bh + 2);
            }
        }

        if (kt == qt) {   // causal mask on diagonal tile
            int r0l = w*16 + (lane >> 2);
            int c0l = (lane & 3)*2;
            #pragma unroll
            for (int nt = 0; nt < 8; nt++) {
                int c = nt*8 + c0l;
                if (c     > r0l)     s[nt][0] = -1e9f;
                if (c + 1 > r0l)     s[nt][1] = -1e9f;
                if (c     > r0l + 8) s[nt][2] = -1e9f;
                if (c + 1 > r0l + 8) s[nt][3] = -1e9f;
            }
        }

        // online softmax
        float rm0 = -1e9f, rm1 = -1e9f;
        #pragma unroll
        for (int nt = 0; nt < 8; nt++) {
            rm0 = fmaxf(rm0, fmaxf(s[nt][0], s[nt][1]));
            rm1 = fmaxf(rm1, fmaxf(s[nt][2], s[nt][3]));
        }
        rm0 = fmaxf(rm0, __shfl_xor_sync(0xffffffffu, rm0, 1));
        rm0 = fmaxf(rm0, __shfl_xor_sync(0xffffffffu, rm0, 2));
        rm1 = fmaxf(rm1, __shfl_xor_sync(0xffffffffu, rm1, 1));
        rm1 = fmaxf(rm1, __shfl_xor_sync(0xffffffffu, rm1, 2));
        float mn0 = fmaxf(m0, rm0), mn1 = fmaxf(m1, rm1);
        float corr0 = __expf(m0 - mn0), corr1 = __expf(m1 - mn1);
        m0 = mn0; m1 = mn1;
        float rs0 = 0.f, rs1 = 0.f;
        #pragma unroll
        for (int nt = 0; nt < 8; nt++) {
            s[nt][0] = __expf(s[nt][0] - mn0); rs0 += s[nt][0];
            s[nt][1] = __expf(s[nt][1] - mn0); rs0 += s[nt][1];
            s[nt][2] = __expf(s[nt][2] - mn1); rs1 += s[nt][2];
            s[nt][3] = __expf(s[nt][3] - mn1); rs1 += s[nt][3];
        }
        rs0 += __shfl_xor_sync(0xffffffffu, rs0, 1);
        rs0 += __shfl_xor_sync(0xffffffffu, rs0, 2);
        rs1 += __shfl_xor_sync(0xffffffffu, rs1, 1);
        rs1 += __shfl_xor_sync(0xffffffffu, rs1, 2);
        l0 = l0*corr0 + rs0;
        l1 = l1*corr1 + rs1;
        #pragma unroll
        for (int nt = 0; nt < 8; nt++) {
            o[nt][0] *= corr0; o[nt][1] *= corr0;
            o[nt][2] *= corr1; o[nt][3] *= corr1;
        }

        // O += P V
        #pragma unroll
        for (int kc = 0; kc < 4; kc++) {
            uint32_t ap[4];
            ap[0] = packh2(s[2*kc][0],   s[2*kc][1]);
            ap[1] = packh2(s[2*kc][2],   s[2*kc][3]);
            ap[2] = packh2(s[2*kc+1][0], s[2*kc+1][1]);
            ap[3] = packh2(s[2*kc+1][2], s[2*kc+1][3]);
            #pragma unroll
            for (int jj = 0; jj < 4; jj++) {
                int r = kc*16 + (g & 1)*8 + rl8;
                int ccol = jj*16 + (g >> 1)*8;
                uint32_t vb[4];
                ldsm4t(vb, smaddr(&Vsp[r*72 + ccol]));
                mma16816(o[2*jj],   ap, vb);
                mma16816(o[2*jj+1], ap, vb + 2);
            }
        }
    }

    const float inv0 = 1.0f/l0, inv1 = 1.0f/l1;
    const size_t rg = ((size_t)b*TT + qt*64 + w*16 + (lane >> 2))*HH;
    #pragma unroll
    for (int nt = 0; nt < 8; nt++) {
        int c = nt*8 + (lane & 3)*2;
        *(float2*)&out[rg + c] = make_float2(o[nt][0]*inv0, o[nt][1]*inv0);
        *(float2*)&out[rg + 8*HH + c] = make_float2(o[nt][2]*inv1, o[nt][3]*inv1);
    }
}

extern "C" void kernel_launch(void* const* d_in, const int* in_sizes, int n_in,
                              void* d_out, int out_size) {
    const float* x  = (const float*)d_in[0];
    const float* Wk = (const float*)d_in[1];
    const float* Wq = (const float*)d_in[2];
    const float* Wv = (const float*)d_in[3];
    float* out = (float*)d_out;

    proj_kernel<<<(BB*TT)/64, 256>>>(x, Wk, Wq, Wv);

    static int smem_set = 0;
    if (!smem_set) {
        cudaFuncSetAttribute(attn_kernel,
                             cudaFuncAttributeMaxDynamicSharedMemorySize,
                             ATT_SMEM_BYTES);
        smem_set = 1;
    }
    attn_kernel<<<dim3(TT/64, BB), 128, ATT_SMEM_BYTES>>>(out);
}

// round 6
// speedup vs baseline: 4.3455x; 1.2116x over previous
#include <cuda_runtime.h>
#include <cuda_fp16.h>
#include <cstdint>

#define BB 8
#define TT 2048
#define CC 1024
#define HH 64
#define NQT 32            // T/64 q-tiles
#define SPL 4             // kv splits

__device__ __align__(16) __half g_qh[BB*TT*HH];
__device__ __align__(16) __half g_ql[BB*TT*HH];
__device__ __align__(16) __half g_kh[BB*TT*HH];
__device__ __align__(16) __half g_vh[BB*TT*HH];
__device__ __align__(16) __half g_wf[CC*192];          // fused fp16 W (K|Q|V)
__device__ float g_pO[BB*NQT*SPL*64*64];               // unnormalized partials
__device__ float g_pM[BB*NQT*SPL*64];
__device__ float g_pL[BB*NQT*SPL*64];

__device__ __forceinline__ uint32_t smaddr(const void* p) {
    return (uint32_t)__cvta_generic_to_shared(p);
}
__device__ __forceinline__ void ldsm4(uint32_t r[4], uint32_t a) {
    asm volatile("ldmatrix.sync.aligned.m8n8.x4.shared.b16 {%0,%1,%2,%3}, [%4];\n"
        : "=r"(r[0]), "=r"(r[1]), "=r"(r[2]), "=r"(r[3]) : "r"(a));
}
__device__ __forceinline__ void ldsm4t(uint32_t r[4], uint32_t a) {
    asm volatile("ldmatrix.sync.aligned.m8n8.x4.trans.shared.b16 {%0,%1,%2,%3}, [%4];\n"
        : "=r"(r[0]), "=r"(r[1]), "=r"(r[2]), "=r"(r[3]) : "r"(a));
}
__device__ __forceinline__ void mma16816(float d[4], const uint32_t a[4], const uint32_t b[2]) {
    asm volatile("mma.sync.aligned.m16n8k16.row.col.f32.f16.f16.f32 "
        "{%0,%1,%2,%3}, {%4,%5,%6,%7}, {%8,%9}, {%0,%1,%2,%3};\n"
        : "+f"(d[0]), "+f"(d[1]), "+f"(d[2]), "+f"(d[3])
        : "r"(a[0]), "r"(a[1]), "r"(a[2]), "r"(a[3]), "r"(b[0]), "r"(b[1]));
}
__device__ __forceinline__ uint32_t packh2(float a, float b) {
    __half2 h = __floats2half2_rn(a, b);
    return *reinterpret_cast<uint32_t*>(&h);
}
#define CPA16(dst, src) \
    asm volatile("cp.async.cg.shared.global [%0], [%1], 16;" :: "r"(dst), "l"(src))

// ---------------------------------------------------------------------------
// W prep: fuse Wk|Wq|Wv into fp16 [k][192]
// ---------------------------------------------------------------------------
__global__ void wprep_kernel(const float* __restrict__ Wk,
                             const float* __restrict__ Wq,
                             const float* __restrict__ Wv)
{
    int idx = blockIdx.x*256 + threadIdx.x;       // 196608
    int k = idx / 192, n = idx % 192;
    int m = n >> 6, h = n & 63;
    const float* W = (m == 0) ? Wk : (m == 1) ? Wq : Wv;
    g_wf[idx] = __float2half_rn(W[(size_t)k*HH + h]);
}

// ---------------------------------------------------------------------------
// Projection with cp.async double-buffered staging.
// smem: xs hi/lo [64][40]h @0 (10240B), xf32 2x[64][32]f @10240,
//       ws 2x[32][200]h @26624.  Total 52224 B.
// ---------------------------------------------------------------------------
#define PROJ_SMEM 52224

__device__ __forceinline__ void proj_prefetch(char* sm, int buf, int k0,
                                              const float* __restrict__ x,
                                              int row0, int tid)
{
    char* xf = sm + 10240 + buf*8192;
    char* wf = sm + 26624 + buf*12800;
    #pragma unroll
    for (int i = 0; i < 2; i++) {                 // x: 64x32 fp32
        int j = tid + i*256; int r = j >> 3, c4 = (j & 7)*4;
        CPA16(smaddr(xf + r*128 + c4*4), &x[(size_t)(row0 + r)*CC + k0 + c4]);
    }
    #pragma unroll
    for (int i = 0; i < 3; i++) {                 // W: 32x192 fp16
        int j = tid + i*256; int r = j / 24, c8 = (j % 24)*8;
        CPA16(smaddr(wf + r*400 + c8*2), &g_wf[(size_t)(k0 + r)*192 + c8]);
    }
}

__global__ __launch_bounds__(256, 2) void proj_kernel(const float* __restrict__ x)
{
    extern __shared__ char sm[];
    __half (*xsh)[40] = (__half (*)[40])sm;
    __half (*xsl)[40] = (__half (*)[40])(sm + 5120);

    const int tid = threadIdx.x;
    const int wid = tid >> 5, lane = tid & 31;
    const int wg = wid >> 2, w4 = wid & 3;
    const int row0 = blockIdx.x * 64;

    float acc[12][4];
    #pragma unroll
    for (int j = 0; j < 12; j++)
        #pragma unroll
        for (int e = 0; e < 4; e++) acc[j][e] = 0.f;

    proj_prefetch(sm, 0, 0, x, row0, tid);
    asm volatile("cp.async.commit_group;");

    #pragma unroll 1
    for (int c = 0; c < 32; c++) {
        const int buf = c & 1;
        __syncthreads();                          // all warps done with prev bufs
        if (c + 1 < 32) {
            proj_prefetch(sm, buf ^ 1, (c+1)*32, x, row0, tid);
            asm volatile("cp.async.commit_group;");
            asm volatile("cp.async.wait_group 1;");
        } else {
            asm volatile("cp.async.wait_group 0;");
        }
        __syncthreads();
        {   // convert x fp32 -> hi/lo fp16
            const float* xf = (const float*)(sm + 10240 + buf*8192);
            #pragma unroll
            for (int i = 0; i < 8; i++) {
                int idx = tid + i*256; int r = idx >> 5, cc = idx & 31;
                float f = xf[r*32 + cc];
                __half h = __float2half_rn(f);
                xsh[r][cc] = h;
                xsl[r][cc] = __float2half_rn(f - __half2float(h));
            }
        }
        __syncthreads();
        const __half* ws = (const __half*)(sm + 26624 + buf*12800);
        #pragma unroll
        for (int sub = 0; sub < 2; sub++) {
            uint32_t ah[4], al[4];
            int ar = w4*16 + (lane & 15), ac = sub*16 + ((lane >> 4) << 3);
            ldsm4(ah, smaddr(&xsh[ar][ac]));
            ldsm4(al, smaddr(&xsl[ar][ac]));
            int g = lane >> 3, rl = lane & 7;
            int br = sub*16 + (g & 1)*8 + rl;
            #pragma unroll
            for (int j = 0; j < 6; j++) {
                int bc = wg*96 + j*16 + (g >> 1)*8;
                uint32_t bh[4];
                ldsm4t(bh, smaddr(&ws[br*200 + bc]));
                mma16816(acc[2*j],   ah, bh);
                mma16816(acc[2*j],   al, bh);
                mma16816(acc[2*j+1], ah, bh + 2);
                mma16816(acc[2*j+1], al, bh + 2);
            }
        }
    }

    const int rl = lane >> 2, q2 = (lane & 3)*2;
    #pragma unroll
    for (int j = 0; j < 6; j++) {
        #pragma unroll
        for (int h = 0; h < 2; h++) {
            int n = wg*96 + j*16 + h*8 + q2;
            int m = n >> 6, hc = n & 63;
            #pragma unroll
            for (int er = 0; er < 2; er++) {
                float v0 = acc[2*j+h][er*2], v1 = acc[2*j+h][er*2+1];
                size_t off = (size_t)(row0 + w4*16 + rl + er*8)*HH + hc;
                if (m == 2) {
                    *(__half2*)&g_vh[off] = __floats2half2_rn(v0, v1);
                } else if (m == 0) {
                    *(__half2*)&g_kh[off] = __floats2half2_rn(v0, v1);
                } else {
                    v0 *= 0.125f; v1 *= 0.125f;
                    __half h0 = __float2half_rn(v0), h1 = __float2half_rn(v1);
                    *(__half2*)&g_qh[off] = __halves2half2(h0, h1);
                    *(__half2*)&g_ql[off] = __halves2half2(
                        __float2half_rn(v0 - __half2float(h0)),
                        __float2half_rn(v1 - __half2float(h1)));
                }
            }
        }
    }
}

// ---------------------------------------------------------------------------
// Flash attention, split-KV: CTA (qt, j) does kt = j, j+SPL, ... <= qt,
// writes unnormalized O + (m, l) partials.
// ---------------------------------------------------------------------------
#define ATT_SMEM_BYTES ((4608*2 + 2*9216) * 2)    // 55296

__device__ __forceinline__ void kv_prefetch(__half* sh, int buf, size_t gbase,
                                            int tid)
{
    __half* base = sh + 9216 + buf*9216;
    #pragma unroll
    for (int i = 0; i < 8; i++) {
        int j = tid + i*128;
        int surf = j >> 9, rc = j & 511;
        int r = rc >> 3, c = (rc & 7)*8;
        CPA16(smaddr(base + surf*4608 + r*72 + c),
              (surf ? g_vh : g_kh) + gbase + r*64 + c);
    }
}

__global__ __launch_bounds__(128) void attn_kernel()
{
    extern __shared__ __half sh[];
    __half* Qh = sh;
    __half* Ql = sh + 4608;

    const int tid = threadIdx.x;
    const int w = tid >> 5, lane = tid & 31;
    const int qt = NQT - 1 - ((int)blockIdx.x >> 2);   // big tiles first
    const int js = blockIdx.x & 3;
    const int b = blockIdx.y;
    const int chunk = (b*NQT + qt)*SPL + js;
    float* po = g_pO + (size_t)chunk*4096;

    if (js > qt) {      // no tiles: zero partials
        #pragma unroll
        for (int i = 0; i < 32; i++) po[tid + i*128] = 0.f;
        if (tid < 64) { g_pM[chunk*64 + tid] = -1e9f; g_pL[chunk*64 + tid] = 0.f; }
        return;
    }

    const size_t kvb = (size_t)b*TT*HH;
    kv_prefetch(sh, 0, kvb + (size_t)js*64*HH, tid);
    asm volatile("cp.async.commit_group;");

    {   // Q tiles
        const size_t qb = kvb + (size_t)qt*64*HH;
        #pragma unroll
        for (int i = 0; i < 4; i++) {
            int idx = tid + i*128; int r = idx >> 3, c = (idx & 7)*8;
            *(int4*)&Qh[r*72 + c] = *(const int4*)&g_qh[qb + r*64 + c];
            *(int4*)&Ql[r*72 + c] = *(const int4*)&g_ql[qb + r*64 + c];
        }
    }
    __syncthreads();

    uint32_t aqh[4][4], aql[4][4];
    #pragma unroll
    for (int kc = 0; kc < 4; kc++) {
        int r = w*16 + (lane & 15), c = kc*16 + ((lane >> 4) << 3);
        ldsm4(aqh[kc], smaddr(&Qh[r*72 + c]));
        ldsm4(aql[kc], smaddr(&Ql[r*72 + c]));
    }

    float o[8][4];
    #pragma unroll
    for (int nt = 0; nt < 8; nt++)
        #pragma unroll
        for (int e = 0; e < 4; e++) o[nt][e] = 0.f;
    float m0 = -1e9f, m1 = -1e9f, l0 = 0.f, l1 = 0.f;

    #pragma unroll 1
    for (int kt = js; kt <= qt; kt += SPL) {
        __syncthreads();
        if (kt + SPL <= qt) {
            kv_prefetch(sh, ((kt - js) >> 2 & 1) ^ 1,
                        kvb + (size_t)(kt + SPL)*64*HH, tid);
            asm volatile("cp.async.commit_group;");
            asm volatile("cp.async.wait_group 1;");
        } else {
            asm volatile("cp.async.wait_group 0;");
        }
        __syncthreads();

        __half* Khp = sh + 9216 + ((kt - js) >> 2 & 1)*9216;
        __half* Vsp = Khp + 4608;

        float s[8][4];
        #pragma unroll
        for (int nt = 0; nt < 8; nt++)
            #pragma unroll
            for (int e = 0; e < 4; e++) s[nt][e] = 0.f;
        const int g = lane >> 3, rl8 = lane & 7;
        #pragma unroll
        for (int kc = 0; kc < 4; kc++) {
            #pragma unroll
            for (int jj = 0; jj < 4; jj++) {
                int r = jj*16 + (g >> 1)*8 + rl8;
                int ccol = kc*16 + (g & 1)*8;
                uint32_t bh[4];
                ldsm4(bh, smaddr(&Khp[r*72 + ccol]));
                mma16816(s[2*jj],   aqh[kc], bh);
                mma16816(s[2*jj],   aql[kc], bh);
                mma16816(s[2*jj+1], aqh[kc], bh + 2);
                mma16816(s[2*jj+1], aql[kc], bh + 2);
            }
        }

        if (kt == qt) {
            int r0l = w*16 + (lane >> 2);
            int c0l = (lane & 3)*2;
            #pragma unroll
            for (int nt = 0; nt < 8; nt++) {
                int c = nt*8 + c0l;
                if (c     > r0l)     s[nt][0] = -1e9f;
                if (c + 1 > r0l)     s[nt][1] = -1e9f;
                if (c     > r0l + 8) s[nt][2] = -1e9f;
                if (c + 1 > r0l + 8) s[nt][3] = -1e9f;
            }
        }

        float rm0 = -1e9f, rm1 = -1e9f;
        #pragma unroll
        for (int nt = 0; nt < 8; nt++) {
            rm0 = fmaxf(rm0, fmaxf(s[nt][0], s[nt][1]));
            rm1 = fmaxf(rm1, fmaxf(s[nt][2], s[nt][3]));
        }
        rm0 = fmaxf(rm0, __shfl_xor_sync(0xffffffffu, rm0, 1));
        rm0 = fmaxf(rm0, __shfl_xor_sync(0xffffffffu, rm0, 2));
        rm1 = fmaxf(rm1, __shfl_xor_sync(0xffffffffu, rm1, 1));
        rm1 = fmaxf(rm1, __shfl_xor_sync(0xffffffffu, rm1, 2));
        float mn0 = fmaxf(m0, rm0), mn1 = fmaxf(m1, rm1);
        float corr0 = __expf(m0 - mn0), corr1 = __expf(m1 - mn1);
        m0 = mn0; m1 = mn1;
        float rs0 = 0.f, rs1 = 0.f;
        #pragma unroll
        for (int nt = 0; nt < 8; nt++) {
            s[nt][0] = __expf(s[nt][0] - mn0); rs0 += s[nt][0];
            s[nt][1] = __expf(s[nt][1] - mn0); rs0 += s[nt][1];
            s[nt][2] = __expf(s[nt][2] - mn1); rs1 += s[nt][2];
            s[nt][3] = __expf(s[nt][3] - mn1); rs1 += s[nt][3];
        }
        rs0 += __shfl_xor_sync(0xffffffffu, rs0, 1);
        rs0 += __shfl_xor_sync(0xffffffffu, rs0, 2);
        rs1 += __shfl_xor_sync(0xffffffffu, rs1, 1);
        rs1 += __shfl_xor_sync(0xffffffffu, rs1, 2);
        l0 = l0*corr0 + rs0;
        l1 = l1*corr1 + rs1;
        #pragma unroll
        for (int nt = 0; nt < 8; nt++) {
            o[nt][0] *= corr0; o[nt][1] *= corr0;
            o[nt][2] *= corr1; o[nt][3] *= corr1;
        }

        #pragma unroll
        for (int kc = 0; kc < 4; kc++) {
            uint32_t ap[4];
            ap[0] = packh2(s[2*kc][0],   s[2*kc][1]);
            ap[1] = packh2(s[2*kc][2],   s[2*kc][3]);
            ap[2] = packh2(s[2*kc+1][0], s[2*kc+1][1]);
            ap[3] = packh2(s[2*kc+1][2], s[2*kc+1][3]);
            #pragma unroll
            for (int jj = 0; jj < 4; jj++) {
                int r = kc*16 + (g & 1)*8 + rl8;
                int ccol = jj*16 + (g >> 1)*8;
                uint32_t vb[4];
                ldsm4t(vb, smaddr(&Vsp[r*72 + ccol]));
                mma16816(o[2*jj],   ap, vb);
                mma16816(o[2*jj+1], ap, vb + 2);
            }
        }
    }

    // write unnormalized partials
    const int r0 = w*16 + (lane >> 2);
    #pragma unroll
    for (int nt = 0; nt < 8; nt++) {
        int c = nt*8 + (lane & 3)*2;
        *(float2*)&po[r0*64 + c]     = make_float2(o[nt][0], o[nt][1]);
        *(float2*)&po[(r0+8)*64 + c] = make_float2(o[nt][2], o[nt][3]);
    }
    if ((lane & 3) == 0) {
        g_pM[chunk*64 + r0] = m0;  g_pL[chunk*64 + r0] = l0;
        g_pM[chunk*64 + r0+8] = m1; g_pL[chunk*64 + r0+8] = l1;
    }
}

// ---------------------------------------------------------------------------
// Merge 4 partials per (b, qt).
// ---------------------------------------------------------------------------
__global__ __launch_bounds__(256) void merge_kernel(float* __restrict__ out)
{
    const int qt = blockIdx.x, b = blockIdx.y;
    const int tid = threadIdx.x;
    const int r = tid >> 2, cg = (tid & 3)*16;
    const int c0 = (b*NQT + qt)*SPL;

    float m[SPL], l[SPL];
    float M = -1e30f;
    #pragma unroll
    for (int j = 0; j < SPL; j++) {
        m[j] = g_pM[(c0 + j)*64 + r];
        l[j] = g_pL[(c0 + j)*64 + r];
        M = fmaxf(M, m[j]);
    }
    float wsum = 0.f, wj[SPL];
    #pragma unroll
    for (int j = 0; j < SPL; j++) {
        wj[j] = __expf(m[j] - M);
        wsum += wj[j]*l[j];
    }
    const float inv = 1.0f/wsum;

    #pragma unroll
    for (int cc = 0; cc < 16; cc += 4) {
        float4 a = make_float4(0.f, 0.f, 0.f, 0.f);
        #pragma unroll
        for (int j = 0; j < SPL; j++) {
            float4 p = *(const float4*)&g_pO[(size_t)(c0 + j)*4096 + r*64 + cg + cc];
            a.x += wj[j]*p.x; a.y += wj[j]*p.y;
            a.z += wj[j]*p.z; a.w += wj[j]*p.w;
        }
        a.x *= inv; a.y *= inv; a.z *= inv; a.w *= inv;
        *(float4*)&out[((size_t)b*TT + qt*64 + r)*HH + cg + cc] = a;
    }
}

extern "C" void kernel_launch(void* const* d_in, const int* in_sizes, int n_in,
                              void* d_out, int out_size) {
    const float* x  = (const float*)d_in[0];
    const float* Wk = (const float*)d_in[1];
    const float* Wq = (const float*)d_in[2];
    const float* Wv = (const float*)d_in[3];
    float* out = (float*)d_out;

    static int attr_set = 0;
    if (!attr_set) {
        cudaFuncSetAttribute(proj_kernel,
            cudaFuncAttributeMaxDynamicSharedMemorySize, PROJ_SMEM);
        cudaFuncSetAttribute(attn_kernel,
            cudaFuncAttributeMaxDynamicSharedMemorySize, ATT_SMEM_BYTES);
        attr_set = 1;
    }
    wprep_kernel<<<768, 256>>>(Wk, Wq, Wv);
    proj_kernel<<<(BB*TT)/64, 256, PROJ_SMEM>>>(x);
    attn_kernel<<<dim3(NQT*SPL, BB), 128, ATT_SMEM_BYTES>>>();
    merge_kernel<<<dim3(NQT, BB), 256>>>(out);
}